// round 5
// baseline (speedup 1.0000x reference)
#include <cuda_runtime.h>

#define NTHREADS 128

// Species row 0 = H, row 1 = O (padded: mu=0, sg=1)
__constant__ float c_mu[2][9] = {
  {-0.0013891633279463555f, 0.052817133273316774f, 0.139812833597163f, 0.04197082575153015f,
    0.f, 0.f, 0.f, 0.f, 0.f},
  { 0.3869724094534165f, 1.1195726605859562f, 4.597656411500856f, 4.18116756869605f,
   -0.777753667038269f, 0.8991094564592526f, 0.25287442792706855f, 0.f, 0.f}
};
__constant__ float c_sg[2][9] = {
  {0.014984132924379046f, 0.06597323056314336f, 0.05229082868259066f, 0.10317217531939492f,
   1.f, 1.f, 1.f, 1.f, 1.f},
  {0.01648580936203453f, 0.04360467004470585f, 0.10939958699162289f, 0.1452881891452822f,
   0.24744978852384295f, 0.6757096584771374f, 0.15629951845443388f, 1.f, 1.f}
};

// om vector v -> coefficient indices. Vectors 0-3: p (9+3v+k).
// Vectors 4-7: d[v-4][{0,2,5}] (D_REORDER[0:3] = 0,2,5), vectors 8-11: d[v-8][{4,3,1}].
__constant__ int c_omidx[12][3] = {
  { 9, 10, 11}, {12, 13, 14}, {15, 16, 17}, {18, 19, 20},
  {21, 23, 26}, {27, 29, 32}, {33, 35, 38}, {39, 41, 44},
  {25, 24, 22}, {31, 30, 28}, {37, 36, 34}, {43, 42, 40}
};

// triu_indices(12, k=1) row-major
__constant__ unsigned char c_pi[66] = {
  0,0,0,0,0,0,0,0,0,0,0,
  1,1,1,1,1,1,1,1,1,1,
  2,2,2,2,2,2,2,2,2,
  3,3,3,3,3,3,3,3,
  4,4,4,4,4,4,4,
  5,5,5,5,5,5,
  6,6,6,6,6,
  7,7,7,7,
  8,8,8,
  9,9,
  10
};
__constant__ unsigned char c_pj[66] = {
  1,2,3,4,5,6,7,8,9,10,11,
  2,3,4,5,6,7,8,9,10,11,
  3,4,5,6,7,8,9,10,11,
  4,5,6,7,8,9,10,11,
  5,6,7,8,9,10,11,
  6,7,8,9,10,11,
  7,8,9,10,11,
  8,9,10,11,
  9,10,11,
  10,11,
  11
};

// cos/sin of Z_k = k*pi/7, k = 0..7
__constant__ float c_cz[8] = { 1.0f,  0.90096887f,  0.62348980f,  0.22252093f,
                              -0.22252093f, -0.62348980f, -0.90096887f, -1.0f };
__constant__ float c_sz[8] = { 0.0f,  0.43388374f,  0.78183148f,  0.97492791f,
                               0.97492791f,  0.78183148f,  0.43388374f,  0.0f };

__global__ __launch_bounds__(NTHREADS)
void aev_kernel(const float* __restrict__ coeff, const int* __restrict__ species,
                float* __restrict__ out)
{
    __shared__ float sh_sn[9];
    __shared__ float sh_dist[12];
    __shared__ float sh_c[66], sh_sq[66], sh_av[66];
    __shared__ __align__(16) float sh_sr[336];      // 144 s_aev + 192 r_aev
    __shared__ __align__(16) float sh_f1[528];      // 2*f1 (premultiplied), [pair][z]
    __shared__ __align__(16) float sh_f2[528];      // [pair][a]

    const int blk = blockIdx.x;      // one block per atom
    const int t   = threadIdx.x;
    const float* cin = coeff + (size_t)blk * 45;

    // ---- stage 1 (single parallel region, no prior sync):
    //   t <  66: pair scalars c, sin(theta), av — self-sufficient from gmem
    //   t <  78: the 12 distances (for r_aev)
    //   t <  87: the 9 normalized s coefficients
    if (t < 66) {
        int i = c_pi[t], j = c_pj[t];
        float xi = cin[c_omidx[i][0]], yi = cin[c_omidx[i][1]], zi = cin[c_omidx[i][2]];
        float xj = cin[c_omidx[j][0]], yj = cin[c_omidx[j][1]], zj = cin[c_omidx[j][2]];
        float di2 = fmaf(xi, xi, fmaf(yi, yi, zi * zi));
        float dj2 = fmaf(xj, xj, fmaf(yj, yj, zj * zj));
        float dij = fmaf(xi, xj, fmaf(yi, yj, zi * zj));
        bool zmi = (fabsf(xi) < 1e-12f) && (fabsf(yi) < 1e-12f) && (fabsf(zi) < 1e-12f);
        bool zmj = (fabsf(xj) < 1e-12f) && (fabsf(yj) < 1e-12f) && (fabsf(zj) < 1e-12f);
        float invi = zmi ? 0.0f : rsqrtf(di2);
        float invj = zmj ? 0.0f : rsqrtf(dj2);
        float c = 0.9999f * (dij * invi * invj);
        sh_c[t]  = c;
        sh_sq[t] = sqrtf(fmaxf(0.0f, fmaf(-c, c, 1.0f)));   // sin(acos(c))
        sh_av[t] = 0.5f * (sqrtf(di2) + sqrtf(dj2));
    } else if (t < 78) {
        int k = t - 66;
        float x = cin[c_omidx[k][0]], y = cin[c_omidx[k][1]], z = cin[c_omidx[k][2]];
        sh_dist[k] = sqrtf(fmaf(x, x, fmaf(y, y, z * z)));
    } else if (t < 87) {
        int k  = t - 78;
        int sp = (species[blk] == 8) ? 1 : 0;
        sh_sn[k] = (cin[k] - c_mu[sp][k]) / c_sg[sp][k];
    }
    __syncthreads();

    // ---- stage 2: 348 groups of 4 elements; each group shares one scalar and
    // writes one STS.128. Regions (in groups):
    //   [0,36)    s_aev   elems [0,144)   of sh_sr
    //   [36,84)   r_aev   elems [144,336) of sh_sr
    //   [84,216)  f2      elems [0,528)   of sh_f2
    //   [216,348) f1      elems [0,528)   of sh_f1 (premultiplied by 2)
    #pragma unroll
    for (int it = 0; it < 3; ++it) {
        int g = it * 128 + t;
        float4 o;
        if (g < 36) {
            int k = g >> 2, i0 = (g & 3) * 4;
            float b = sh_sn[k];
            float x0 = b - fmaf((float)(i0 + 0), 0.53333333f, -4.0f);
            float x1 = b - fmaf((float)(i0 + 1), 0.53333333f, -4.0f);
            float x2 = b - fmaf((float)(i0 + 2), 0.53333333f, -4.0f);
            float x3 = b - fmaf((float)(i0 + 3), 0.53333333f, -4.0f);
            o.x = __expf(-4.0f * x0 * x0);
            o.y = __expf(-4.0f * x1 * x1);
            o.z = __expf(-4.0f * x2 * x2);
            o.w = __expf(-4.0f * x3 * x3);
            *reinterpret_cast<float4*>(&sh_sr[g * 4]) = o;
        } else if (g < 84) {
            int v = g - 36; int k = v >> 2, i0 = (v & 3) * 4;
            float b = sh_dist[k];
            float x0 = b - (float)(i0 + 0) * 0.13333333f;
            float x1 = b - (float)(i0 + 1) * 0.13333333f;
            float x2 = b - (float)(i0 + 2) * 0.13333333f;
            float x3 = b - (float)(i0 + 3) * 0.13333333f;
            o.x = __expf(-4.0f * x0 * x0);
            o.y = __expf(-4.0f * x1 * x1);
            o.z = __expf(-4.0f * x2 * x2);
            o.w = __expf(-4.0f * x3 * x3);
            *reinterpret_cast<float4*>(&sh_sr[144 + v * 4]) = o;
        } else if (g < 216) {
            int v = g - 84; int p = v >> 1, a0 = (v & 1) * 4;
            float b = sh_av[p];
            float x0 = b - (float)(a0 + 0) * 0.28571429f;
            float x1 = b - (float)(a0 + 1) * 0.28571429f;
            float x2 = b - (float)(a0 + 2) * 0.28571429f;
            float x3 = b - (float)(a0 + 3) * 0.28571429f;
            o.x = __expf(-8.0f * x0 * x0);
            o.y = __expf(-8.0f * x1 * x1);
            o.z = __expf(-8.0f * x2 * x2);
            o.w = __expf(-8.0f * x3 * x3);
            *reinterpret_cast<float4*>(&sh_f2[v * 4]) = o;
        } else if (g < 348) {
            int v = g - 216; int p = v >> 1, z0 = (v & 1) * 4;
            float c = sh_c[p], sq = sh_sq[p];
            #pragma unroll
            for (int d = 0; d < 4; ++d) {
                int z = z0 + d;
                float ct = fmaf(c, c_cz[z], sq * c_sz[z]);  // cos(theta - Z_z)
                float b  = fmaf(0.5f, ct, 0.5f);
                float b2 = b * b;
                float b4 = b2 * b2;
                (&o.x)[d] = 2.0f * (b4 * b4);               // 2 * ((1+cos)/2)^8
            }
            *reinterpret_cast<float4*>(&sh_f1[v * 4]) = o;
        }
    }
    __syncthreads();

    // ---- stage 3: coalesced float4 stores: 84 (s+r) + 1056 angular per atom ----
    float4* out4 = reinterpret_cast<float4*>(out) + (size_t)blk * 1140;
    if (t < 84) out4[t] = reinterpret_cast<const float4*>(sh_sr)[t];

    const float4* f2v = reinterpret_cast<const float4*>(sh_f2);
    #pragma unroll
    for (int it = 0; it < 9; ++it) {
        int w = it * 128 + t;
        if (w < 1056) {
            int pair = w >> 4;
            int rem  = w & 15;                        // = z*2 + half
            float f1 = sh_f1[pair * 8 + (rem >> 1)];  // includes the 2x
            float4 f2 = f2v[pair * 2 + (rem & 1)];
            float4 o;
            o.x = f1 * f2.x; o.y = f1 * f2.y; o.z = f1 * f2.z; o.w = f1 * f2.w;
            out4[84 + w] = o;                         // element = 336 + pair*64 + z*8 + a
        }
    }
}

extern "C" void kernel_launch(void* const* d_in, const int* in_sizes, int n_in,
                              void* d_out, int out_size)
{
    const float* coeff   = (const float*)d_in[0];   // (nconf, natoms, 45) f32
    const int*   species = (const int*)d_in[1];     // (nconf, natoms) i32
    float*       out     = (float*)d_out;           // (nconf, natoms, 4560) f32
    int nblk = in_sizes[1];                         // nconf * natoms atoms
    aev_kernel<<<nblk, NTHREADS>>>(coeff, species, out);
}